// round 15
// baseline (speedup 1.0000x reference)
#include <cuda_runtime.h>
#include <cuda_fp16.h>

#define N_NODES   100000
#define N_EDGES   1600000
#define N_GRAPHS  5000
#define ND        16
#define ED        16
#define HID       20
#define H2        10
#define HP        (HID/2)
#define H2P       (H2/2)
// pa/pb/g_x rows: 64B = two 32B chunks; chunk q holds dim-pairs [5q,5q+5) (10 halves + 12B pad)

// Scratch
__device__ __align__(128) __half g_x [N_NODES * 32];
__device__ __align__(128) __half g_pa[N_NODES * 32];
__device__ __align__(128) __half g_pb[N_NODES * 32];
__device__ float g_g [N_GRAPHS * H2];

// ---- packed f32x2 helpers -------------------------------------------------
__device__ __forceinline__ unsigned long long fma2(unsigned long long a,
                                                   unsigned long long b,
                                                   unsigned long long c) {
    unsigned long long d;
    asm("fma.rn.f32x2 %0, %1, %2, %3;" : "=l"(d) : "l"(a), "l"(b), "l"(c));
    return d;
}
__device__ __forceinline__ unsigned long long bcast2(float x) {
    unsigned long long d;
    asm("mov.b64 %0, {%1, %1};" : "=l"(d) : "f"(x));
    return d;
}
__device__ __forceinline__ float2 unpack2(unsigned long long v) {
    float2 r;
    asm("mov.b64 {%0, %1}, %2;" : "=f"(r.x), "=f"(r.y) : "l"(v));
    return r;
}
__device__ __forceinline__ float2 h2f2(unsigned int h) {
    return __half22float2(*(const __half2*)&h);
}

// 256-bit load (Blackwell) — requires 32B-aligned address
__device__ __forceinline__ void ldg256(const void* p, float r[8]) {
    asm("ld.global.nc.v8.f32 {%0,%1,%2,%3,%4,%5,%6,%7}, [%8];"
        : "=f"(r[0]), "=f"(r[1]), "=f"(r[2]), "=f"(r[3]),
          "=f"(r[4]), "=f"(r[5]), "=f"(r[6]), "=f"(r[7])
        : "l"(p));
}

// ---------------------------------------------------------------------------
// Kernel 1: per-node projections pa = A@Wa, pb = A@Wb  (fp16, split-chunk rows)
// ---------------------------------------------------------------------------
__global__ __launch_bounds__(128) void node_proj_kernel(
        const float* __restrict__ node_attr,
        const float* __restrict__ W_msg) {
    __shared__ __align__(8) float sWa[ND * HID];
    __shared__ __align__(8) float sWb[ND * HID];
    for (int i = threadIdx.x; i < ND * HID; i += blockDim.x) {
        sWa[i] = W_msg[i];
        sWb[i] = W_msg[ND * HID + i];
    }
    __syncthreads();
    const unsigned long long* wa2 = (const unsigned long long*)sWa;
    const unsigned long long* wb2 = (const unsigned long long*)sWb;

    int n = blockIdx.x * blockDim.x + threadIdx.x;

    if (n < (N_GRAPHS * H2) / 4)
        ((float4*)g_g)[n] = make_float4(0.f, 0.f, 0.f, 0.f);

    if (n >= N_NODES) return;

    // zero this node's g_x row (full 64B)
    {
        char* xr = (char*)g_x + (size_t)n * 64;
        const uint4 z4 = make_uint4(0u, 0u, 0u, 0u);
        *(uint4*)(xr)      = z4;
        *(uint4*)(xr + 16) = z4;
        *(uint4*)(xr + 32) = z4;
        *(uint4*)(xr + 48) = z4;
    }

    float a[ND];
    const float4* ap = (const float4*)(node_attr + (size_t)n * ND);
#pragma unroll
    for (int q = 0; q < 4; q++) {
        float4 v = ap[q];
        a[4*q+0] = v.x; a[4*q+1] = v.y; a[4*q+2] = v.z; a[4*q+3] = v.w;
    }

    unsigned long long acc[HP];
    unsigned int u[HP];

    // pa
#pragma unroll
    for (int p = 0; p < HP; p++) acc[p] = 0ull;
#pragma unroll
    for (int k = 0; k < ND; k++) {
        unsigned long long ak = bcast2(a[k]);
#pragma unroll
        for (int p = 0; p < HP; p++) acc[p] = fma2(ak, wa2[k * HP + p], acc[p]);
    }
#pragma unroll
    for (int p = 0; p < HP; p++) {
        float2 t = unpack2(acc[p]);
        __half2 h = __float22half2_rn(t);
        u[p] = *(unsigned int*)&h;
    }
    {   // split-chunk layout: pairs 0-4 at +0, pairs 5-9 at +32
        char* row = (char*)g_pa + (size_t)n * 64;
        *(uint4*)(row +  0) = make_uint4(u[0], u[1], u[2], u[3]);
        *(unsigned int*)(row + 16) = u[4];
        *(uint4*)(row + 32) = make_uint4(u[5], u[6], u[7], u[8]);
        *(unsigned int*)(row + 48) = u[9];
    }

    // pb
#pragma unroll
    for (int p = 0; p < HP; p++) acc[p] = 0ull;
#pragma unroll
    for (int k = 0; k < ND; k++) {
        unsigned long long ak = bcast2(a[k]);
#pragma unroll
        for (int p = 0; p < HP; p++) acc[p] = fma2(ak, wb2[k * HP + p], acc[p]);
    }
#pragma unroll
    for (int p = 0; p < HP; p++) {
        float2 t = unpack2(acc[p]);
        __half2 h = __float22half2_rn(t);
        u[p] = *(unsigned int*)&h;
    }
    {
        char* row = (char*)g_pb + (size_t)n * 64;
        *(uint4*)(row +  0) = make_uint4(u[0], u[1], u[2], u[3]);
        *(unsigned int*)(row + 16) = u[4];
        *(uint4*)(row + 32) = make_uint4(u[5], u[6], u[7], u[8]);
        *(unsigned int*)(row + 48) = u[9];
    }
}

// ---------------------------------------------------------------------------
// Kernel 2: edge message + scatter-sum. 2 threads per edge; thread q owns
// dim-pairs [5q, 5q+5). One ldg256 per gather row per thread; lane pairs
// share the row's 128B line.
// ---------------------------------------------------------------------------
__global__ __launch_bounds__(256) void edge_kernel(
        const int*   __restrict__ edge_index,
        const float* __restrict__ edge_attr,
        const float* __restrict__ W_msg,
        const float* __restrict__ b_msg) {
    __shared__ __align__(8) float sWe[ED * HID];
    __shared__ __align__(8) float sb[HID];
    for (int i = threadIdx.x; i < ED * HID; i += blockDim.x)
        sWe[i] = W_msg[2 * ND * HID + i];
    for (int i = threadIdx.x; i < HID; i += blockDim.x)
        sb[i] = b_msg[i];
    __syncthreads();
    const unsigned long long* we2 = (const unsigned long long*)sWe;
    const unsigned long long* sb2 = (const unsigned long long*)sb;

    int t = blockIdx.x * blockDim.x + threadIdx.x;
    int e = t >> 1;
    int q = t & 1;
    if (e >= N_EDGES) {
        cudaGridDependencySynchronize();
        return;
    }

    // inputs (pre-sync): indices + full edge_attr row (lane pairs broadcast)
    int src = __ldg(edge_index + e);
    int dst = __ldg(edge_index + N_EDGES + e);
    float ea[ED];
    ldg256(edge_attr + (size_t)e * ED, ea);
    ldg256(edge_attr + (size_t)e * ED + 8, ea + 8);

    // We matmul for this thread's 5 pairs
    unsigned long long acc[5];
#pragma unroll
    for (int p = 0; p < 5; p++) acc[p] = sb2[5 * q + p];
#pragma unroll
    for (int k = 0; k < ED; k++) {
        unsigned long long b = bcast2(ea[k]);
#pragma unroll
        for (int p = 0; p < 5; p++)
            acc[p] = fma2(b, we2[k * HP + 5 * q + p], acc[p]);
    }

    cudaGridDependencySynchronize();   // wait for node_proj

    // gathers: one 32B chunk each from pa[src], pb[dst]
    const char* par = (const char*)g_pa + (size_t)src * 64 + 32 * q;
    const char* pbr = (const char*)g_pb + (size_t)dst * 64 + 32 * q;
    float A8[8], B8[8];
    ldg256(par, A8);
    ldg256(pbr, B8);

    unsigned int au[5] = {
        __float_as_uint(A8[0]), __float_as_uint(A8[1]), __float_as_uint(A8[2]),
        __float_as_uint(A8[3]), __float_as_uint(A8[4])};
    unsigned int bu[5] = {
        __float_as_uint(B8[0]), __float_as_uint(B8[1]), __float_as_uint(B8[2]),
        __float_as_uint(B8[3]), __float_as_uint(B8[4])};

    unsigned int mh[5];
#pragma unroll
    for (int p = 0; p < 5; p++) {
        float2 c = unpack2(acc[p]);
        float2 fa = h2f2(au[p]);
        float2 fb = h2f2(bu[p]);
        float2 mm;
        mm.x = fmaxf(c.x + fa.x + fb.x, 0.f);
        mm.y = fmaxf(c.y + fa.y + fb.y, 0.f);
        __half2 h = __float22half2_rn(mm);
        mh[p] = *(unsigned int*)&h;
    }

    char* xr = (char*)g_x + (size_t)dst * 64 + 32 * q;
    asm volatile("red.global.add.noftz.v4.f16x2 [%0], {%1,%2,%3,%4};"
                 :: "l"(xr), "r"(mh[0]), "r"(mh[1]), "r"(mh[2]), "r"(mh[3]) : "memory");
    asm volatile("red.global.add.noftz.f16x2 [%0], %1;"
                 :: "l"(xr + 16), "r"(mh[4]) : "memory");
}

// ---------------------------------------------------------------------------
// Kernel 3: node MLP + graph pooling (split-chunk g_x reads)
// ---------------------------------------------------------------------------
__global__ __launch_bounds__(128) void node_mlp_kernel(
        const int*   __restrict__ batch,
        const float* __restrict__ W1,
        const float* __restrict__ b1) {
    __shared__ __align__(8) float sW[HID * H2];
    __shared__ __align__(8) float sb[H2];
    for (int i = threadIdx.x; i < HID * H2; i += blockDim.x) sW[i] = W1[i];
    for (int i = threadIdx.x; i < H2; i += blockDim.x) sb[i] = b1[i];
    __syncthreads();
    const unsigned long long* w2 = (const unsigned long long*)sW;
    const unsigned long long* sb2 = (const unsigned long long*)sb;

    int n = blockIdx.x * blockDim.x + threadIdx.x;
    if (n >= N_NODES) {
        cudaGridDependencySynchronize();
        return;
    }

    int b = __ldg(batch + n);     // input, safe before sync

    cudaGridDependencySynchronize();   // wait for edge_kernel's g_x

    const char* xrow = (const char*)g_x + (size_t)n * 64;
    float X0[8], X1[8];
    ldg256(xrow, X0);
    ldg256(xrow + 32, X1);
    unsigned int xu[HP] = {
        __float_as_uint(X0[0]), __float_as_uint(X0[1]), __float_as_uint(X0[2]),
        __float_as_uint(X0[3]), __float_as_uint(X0[4]),
        __float_as_uint(X1[0]), __float_as_uint(X1[1]), __float_as_uint(X1[2]),
        __float_as_uint(X1[3]), __float_as_uint(X1[4])};

    float x[HID];
#pragma unroll
    for (int p = 0; p < HP; p++) {
        float2 t = h2f2(xu[p]);
        x[2*p] = t.x; x[2*p+1] = t.y;
    }

    unsigned long long acc[H2P];
#pragma unroll
    for (int p = 0; p < H2P; p++) acc[p] = sb2[p];
#pragma unroll
    for (int k = 0; k < HID; k++) {
        unsigned long long xk = bcast2(x[k]);
#pragma unroll
        for (int p = 0; p < H2P; p++) acc[p] = fma2(xk, w2[k * H2P + p], acc[p]);
    }

    float y[H2];
#pragma unroll
    for (int p = 0; p < H2P; p++) {
        float2 t = unpack2(acc[p]);
        y[2*p]   = fmaxf(t.x, 0.f);
        y[2*p+1] = fmaxf(t.y, 0.f);
    }

    float* gr = g_g + (size_t)b * H2;
#pragma unroll
    for (int qq = 0; qq < 5; qq++) {
        asm volatile("red.global.add.v2.f32 [%0], {%1,%2};"
                     :: "l"(gr + 2*qq), "f"(y[2*qq]), "f"(y[2*qq+1])
                     : "memory");
    }
}

// ---------------------------------------------------------------------------
// Kernel 4: graph MLP (PDL consumer of node_mlp)
// ---------------------------------------------------------------------------
__global__ __launch_bounds__(256) void graph_mlp_kernel(
        const float* __restrict__ W2,
        const float* __restrict__ b2,
        const float* __restrict__ W3,
        const float* __restrict__ b3,
        float* __restrict__ out) {
    __shared__ float sW2[H2 * H2];
    __shared__ float sb2[H2];
    __shared__ float sW3[H2];
    __shared__ float sb3;
    for (int i = threadIdx.x; i < H2 * H2; i += blockDim.x) sW2[i] = W2[i];
    if (threadIdx.x < H2) { sb2[threadIdx.x] = b2[threadIdx.x]; sW3[threadIdx.x] = W3[threadIdx.x]; }
    if (threadIdx.x == 0) sb3 = b3[0];
    __syncthreads();

    cudaGridDependencySynchronize();   // wait for node_mlp's g_g

    int g = blockIdx.x * blockDim.x + threadIdx.x;
    if (g >= N_GRAPHS) return;

    float v[H2];
    const float2* gp = (const float2*)(g_g + (size_t)g * H2);
#pragma unroll
    for (int qq = 0; qq < 5; qq++) {
        float2 t = gp[qq];
        v[2*qq] = t.x; v[2*qq+1] = t.y;
    }

    float o = sb3;
#pragma unroll
    for (int j = 0; j < H2; j++) {
        float h = sb2[j];
#pragma unroll
        for (int k = 0; k < H2; k++) h = fmaf(v[k], sW2[k * H2 + j], h);
        o = fmaf(fmaxf(h, 0.f), sW3[j], o);
    }
    out[g] = o;
}

// ---------------------------------------------------------------------------
extern "C" void kernel_launch(void* const* d_in, const int* in_sizes, int n_in,
                              void* d_out, int out_size) {
    const int*   edge_index = (const int*)  d_in[0];
    const float* node_attr  = (const float*)d_in[1];
    const float* edge_attr  = (const float*)d_in[2];
    const int*   batch      = (const int*)  d_in[3];
    const float* W_msg      = (const float*)d_in[4];
    const float* b_msg      = (const float*)d_in[5];
    const float* W1         = (const float*)d_in[6];
    const float* b1         = (const float*)d_in[7];
    const float* W2         = (const float*)d_in[8];
    const float* b2         = (const float*)d_in[9];
    const float* W3         = (const float*)d_in[10];
    const float* b3         = (const float*)d_in[11];
    float* out = (float*)d_out;

    node_proj_kernel<<<(N_NODES + 127) / 128, 128>>>(node_attr, W_msg);

    cudaLaunchAttribute attr[1];
    attr[0].id = cudaLaunchAttributeProgrammaticStreamSerialization;
    attr[0].val.programmaticStreamSerializationAllowed = 1;

    {
        cudaLaunchConfig_t cfg = {};
        cfg.gridDim  = dim3((2 * N_EDGES + 255) / 256);
        cfg.blockDim = dim3(256);
        cfg.attrs = attr; cfg.numAttrs = 1;
        cudaLaunchKernelEx(&cfg, edge_kernel, edge_index, edge_attr, W_msg, b_msg);
    }
    {
        cudaLaunchConfig_t cfg = {};
        cfg.gridDim  = dim3((N_NODES + 127) / 128);
        cfg.blockDim = dim3(128);
        cfg.attrs = attr; cfg.numAttrs = 1;
        cudaLaunchKernelEx(&cfg, node_mlp_kernel, batch, W1, b1);
    }
    {
        cudaLaunchConfig_t cfg = {};
        cfg.gridDim  = dim3((N_GRAPHS + 255) / 256);
        cfg.blockDim = dim3(256);
        cfg.attrs = attr; cfg.numAttrs = 1;
        cudaLaunchKernelEx(&cfg, graph_mlp_kernel, W2, b2, W3, b3, out);
    }
}

// round 16
// speedup vs baseline: 1.6670x; 1.6670x over previous
#include <cuda_runtime.h>
#include <cuda_fp16.h>

#define N_NODES   100000
#define N_EDGES   1600000
#define N_GRAPHS  5000
#define ND        16
#define ED        16
#define HID       20
#define H2        10
#define HP        (HID/2)
#define H2P       (H2/2)
#define PH_STRIDE 32        // half stride per pa/pb row: 64B
#define XH_STRIDE 32        // half stride per g_x row: 64B

// Scratch
__device__ __align__(128) __half g_x [N_NODES * XH_STRIDE];  // fp16 accumulators
__device__ __align__(128) __half g_pa[N_NODES * PH_STRIDE];
__device__ __align__(128) __half g_pb[N_NODES * PH_STRIDE];
__device__ float g_g [N_GRAPHS * H2];

// ---- packed f32x2 helpers -------------------------------------------------
__device__ __forceinline__ unsigned long long fma2(unsigned long long a,
                                                   unsigned long long b,
                                                   unsigned long long c) {
    unsigned long long d;
    asm("fma.rn.f32x2 %0, %1, %2, %3;" : "=l"(d) : "l"(a), "l"(b), "l"(c));
    return d;
}
__device__ __forceinline__ unsigned long long bcast2(float x) {
    unsigned long long d;
    asm("mov.b64 %0, {%1, %1};" : "=l"(d) : "f"(x));
    return d;
}
__device__ __forceinline__ float2 unpack2(unsigned long long v) {
    float2 r;
    asm("mov.b64 {%0, %1}, %2;" : "=f"(r.x), "=f"(r.y) : "l"(v));
    return r;
}
__device__ __forceinline__ float2 h2f2(unsigned int h) {
    return __half22float2(*(const __half2*)&h);
}

// 256-bit load (Blackwell) — requires 32B-aligned address
__device__ __forceinline__ void ldg256(const void* p, float r[8]) {
    asm("ld.global.nc.v8.f32 {%0,%1,%2,%3,%4,%5,%6,%7}, [%8];"
        : "=f"(r[0]), "=f"(r[1]), "=f"(r[2]), "=f"(r[3]),
          "=f"(r[4]), "=f"(r[5]), "=f"(r[6]), "=f"(r[7])
        : "l"(p));
}
__device__ __forceinline__ float2 ldg64(const void* p) {
    float2 r;
    asm("ld.global.nc.v2.f32 {%0,%1}, [%2];" : "=f"(r.x), "=f"(r.y) : "l"(p));
    return r;
}

// ---------------------------------------------------------------------------
// Kernel 1: per-node projections pa = A@Wa, pb = A@Wb  (fp16 out, + zeroing)
// ---------------------------------------------------------------------------
__global__ __launch_bounds__(128) void node_proj_kernel(
        const float* __restrict__ node_attr,
        const float* __restrict__ W_msg) {
    __shared__ __align__(8) float sWa[ND * HID];
    __shared__ __align__(8) float sWb[ND * HID];
    for (int i = threadIdx.x; i < ND * HID; i += blockDim.x) {
        sWa[i] = W_msg[i];
        sWb[i] = W_msg[ND * HID + i];
    }
    __syncthreads();
    const unsigned long long* wa2 = (const unsigned long long*)sWa;
    const unsigned long long* wb2 = (const unsigned long long*)sWb;

    int n = blockIdx.x * blockDim.x + threadIdx.x;

    if (n < (N_GRAPHS * H2) / 4)
        ((float4*)g_g)[n] = make_float4(0.f, 0.f, 0.f, 0.f);

    if (n >= N_NODES) return;

    // zero this node's fp16 g_x row
    {
        char* xr = (char*)g_x + (size_t)n * 64;
        const uint4 z4 = make_uint4(0u, 0u, 0u, 0u);
        *(uint4*)(xr)      = z4;
        *(uint4*)(xr + 16) = z4;
        *(uint2*)(xr + 32) = make_uint2(0u, 0u);
    }

    float a[ND];
    const float4* ap = (const float4*)(node_attr + (size_t)n * ND);
#pragma unroll
    for (int q = 0; q < 4; q++) {
        float4 v = ap[q];
        a[4*q+0] = v.x; a[4*q+1] = v.y; a[4*q+2] = v.z; a[4*q+3] = v.w;
    }

    unsigned long long acc[HP];
    unsigned int u[HP];

    // pa
#pragma unroll
    for (int p = 0; p < HP; p++) acc[p] = 0ull;
#pragma unroll
    for (int k = 0; k < ND; k++) {
        unsigned long long ak = bcast2(a[k]);
#pragma unroll
        for (int p = 0; p < HP; p++) acc[p] = fma2(ak, wa2[k * HP + p], acc[p]);
    }
#pragma unroll
    for (int p = 0; p < HP; p++) {
        float2 t = unpack2(acc[p]);
        __half2 h = __float22half2_rn(t);
        u[p] = *(unsigned int*)&h;
    }
    {
        char* row = (char*)(g_pa + (size_t)n * PH_STRIDE);
        *(uint4*)(row +  0) = make_uint4(u[0], u[1], u[2], u[3]);
        *(uint4*)(row + 16) = make_uint4(u[4], u[5], u[6], u[7]);
        *(uint2*)(row + 32) = make_uint2(u[8], u[9]);
    }

    // pb
#pragma unroll
    for (int p = 0; p < HP; p++) acc[p] = 0ull;
#pragma unroll
    for (int k = 0; k < ND; k++) {
        unsigned long long ak = bcast2(a[k]);
#pragma unroll
        for (int p = 0; p < HP; p++) acc[p] = fma2(ak, wb2[k * HP + p], acc[p]);
    }
#pragma unroll
    for (int p = 0; p < HP; p++) {
        float2 t = unpack2(acc[p]);
        __half2 h = __float22half2_rn(t);
        u[p] = *(unsigned int*)&h;
    }
    {
        char* row = (char*)(g_pb + (size_t)n * PH_STRIDE);
        *(uint4*)(row +  0) = make_uint4(u[0], u[1], u[2], u[3]);
        *(uint4*)(row + 16) = make_uint4(u[4], u[5], u[6], u[7]);
        *(uint2*)(row + 32) = make_uint2(u[8], u[9]);
    }
}

// ---------------------------------------------------------------------------
// Kernel 2: edge message + scatter-sum (PDL consumer; gathers issued before
// the We matmul so their L2 latency hides under ~320 cyc of fma work)
// ---------------------------------------------------------------------------
__global__ __launch_bounds__(256) void edge_kernel(
        const int*   __restrict__ edge_index,
        const float* __restrict__ edge_attr,
        const float* __restrict__ W_msg,
        const float* __restrict__ b_msg) {
    __shared__ __align__(8) float sWe[ED * HID];
    __shared__ __align__(8) float sb[HID];
    for (int i = threadIdx.x; i < ED * HID; i += blockDim.x)
        sWe[i] = W_msg[2 * ND * HID + i];
    for (int i = threadIdx.x; i < HID; i += blockDim.x)
        sb[i] = b_msg[i];
    __syncthreads();
    const unsigned long long* we2 = (const unsigned long long*)sWe;
    const unsigned long long* sb2 = (const unsigned long long*)sb;

    int e = blockIdx.x * blockDim.x + threadIdx.x;
    if (e >= N_EDGES) {
        cudaGridDependencySynchronize();
        return;
    }

    // inputs (safe before the dependency sync)
    int src = __ldg(edge_index + e);
    int dst = __ldg(edge_index + N_EDGES + e);
    float ea[ED];
    ldg256(edge_attr + (size_t)e * ED, ea);
    ldg256(edge_attr + (size_t)e * ED + 8, ea + 8);

    // wait for node_proj's g_pa/g_pb, then ISSUE GATHERS FIRST
    cudaGridDependencySynchronize();

    const char* par = (const char*)(g_pa + (size_t)src * PH_STRIDE);
    const char* pbr = (const char*)(g_pb + (size_t)dst * PH_STRIDE);
    float A8[8], B8[8];
    ldg256(par, A8);
    ldg256(pbr, B8);
    float2 A2 = ldg64(par + 32);
    float2 B2 = ldg64(pbr + 32);

    // We matmul overlaps the in-flight gathers
    unsigned long long acc[HP];
#pragma unroll
    for (int p = 0; p < HP; p++) acc[p] = sb2[p];
#pragma unroll
    for (int k = 0; k < ED; k++) {
        unsigned long long b = bcast2(ea[k]);
#pragma unroll
        for (int p = 0; p < HP; p++)
            acc[p] = fma2(b, we2[k * HP + p], acc[p]);
    }

    unsigned int au[HP] = {
        __float_as_uint(A8[0]), __float_as_uint(A8[1]), __float_as_uint(A8[2]),
        __float_as_uint(A8[3]), __float_as_uint(A8[4]), __float_as_uint(A8[5]),
        __float_as_uint(A8[6]), __float_as_uint(A8[7]),
        __float_as_uint(A2.x),  __float_as_uint(A2.y)};
    unsigned int bu[HP] = {
        __float_as_uint(B8[0]), __float_as_uint(B8[1]), __float_as_uint(B8[2]),
        __float_as_uint(B8[3]), __float_as_uint(B8[4]), __float_as_uint(B8[5]),
        __float_as_uint(B8[6]), __float_as_uint(B8[7]),
        __float_as_uint(B2.x),  __float_as_uint(B2.y)};

    unsigned int mh[HP];
#pragma unroll
    for (int p = 0; p < HP; p++) {
        float2 c = unpack2(acc[p]);
        float2 fa = h2f2(au[p]);
        float2 fb = h2f2(bu[p]);
        float2 mm;
        mm.x = fmaxf(c.x + fa.x + fb.x, 0.f);
        mm.y = fmaxf(c.y + fa.y + fb.y, 0.f);
        __half2 h = __float22half2_rn(mm);
        mh[p] = *(unsigned int*)&h;
    }

    char* xr = (char*)g_x + (size_t)dst * 64;
    asm volatile("red.global.add.noftz.v4.f16x2 [%0], {%1,%2,%3,%4};"
                 :: "l"(xr), "r"(mh[0]), "r"(mh[1]), "r"(mh[2]), "r"(mh[3]) : "memory");
    asm volatile("red.global.add.noftz.v4.f16x2 [%0], {%1,%2,%3,%4};"
                 :: "l"(xr + 16), "r"(mh[4]), "r"(mh[5]), "r"(mh[6]), "r"(mh[7]) : "memory");
    asm volatile("red.global.add.noftz.v2.f16x2 [%0], {%1,%2};"
                 :: "l"(xr + 32), "r"(mh[8]), "r"(mh[9]) : "memory");
}

// ---------------------------------------------------------------------------
// Kernel 3: node MLP + graph pooling (PDL consumer of edge_kernel)
// ---------------------------------------------------------------------------
__global__ __launch_bounds__(128) void node_mlp_kernel(
        const int*   __restrict__ batch,
        const float* __restrict__ W1,
        const float* __restrict__ b1) {
    __shared__ __align__(8) float sW[HID * H2];
    __shared__ __align__(8) float sb[H2];
    for (int i = threadIdx.x; i < HID * H2; i += blockDim.x) sW[i] = W1[i];
    for (int i = threadIdx.x; i < H2; i += blockDim.x) sb[i] = b1[i];
    __syncthreads();
    const unsigned long long* w2 = (const unsigned long long*)sW;
    const unsigned long long* sb2 = (const unsigned long long*)sb;

    int n = blockIdx.x * blockDim.x + threadIdx.x;
    if (n >= N_NODES) {
        cudaGridDependencySynchronize();
        return;
    }

    int b = __ldg(batch + n);     // input, safe before sync

    cudaGridDependencySynchronize();   // wait for edge_kernel's g_x

    const char* xrow = (const char*)g_x + (size_t)n * 64;
    float X8[8];
    ldg256(xrow, X8);
    float2 X2 = ldg64(xrow + 32);
    unsigned int xu[HP] = {
        __float_as_uint(X8[0]), __float_as_uint(X8[1]), __float_as_uint(X8[2]),
        __float_as_uint(X8[3]), __float_as_uint(X8[4]), __float_as_uint(X8[5]),
        __float_as_uint(X8[6]), __float_as_uint(X8[7]),
        __float_as_uint(X2.x),  __float_as_uint(X2.y)};

    float x[HID];
#pragma unroll
    for (int p = 0; p < HP; p++) {
        float2 t = h2f2(xu[p]);
        x[2*p] = t.x; x[2*p+1] = t.y;
    }

    unsigned long long acc[H2P];
#pragma unroll
    for (int p = 0; p < H2P; p++) acc[p] = sb2[p];
#pragma unroll
    for (int k = 0; k < HID; k++) {
        unsigned long long xk = bcast2(x[k]);
#pragma unroll
        for (int p = 0; p < H2P; p++) acc[p] = fma2(xk, w2[k * H2P + p], acc[p]);
    }

    float y[H2];
#pragma unroll
    for (int p = 0; p < H2P; p++) {
        float2 t = unpack2(acc[p]);
        y[2*p]   = fmaxf(t.x, 0.f);
        y[2*p+1] = fmaxf(t.y, 0.f);
    }

    float* gr = g_g + (size_t)b * H2;
#pragma unroll
    for (int q = 0; q < 5; q++) {
        asm volatile("red.global.add.v2.f32 [%0], {%1,%2};"
                     :: "l"(gr + 2*q), "f"(y[2*q]), "f"(y[2*q+1])
                     : "memory");
    }
}

// ---------------------------------------------------------------------------
// Kernel 4: graph MLP (PDL consumer of node_mlp)
// ---------------------------------------------------------------------------
__global__ __launch_bounds__(256) void graph_mlp_kernel(
        const float* __restrict__ W2,
        const float* __restrict__ b2,
        const float* __restrict__ W3,
        const float* __restrict__ b3,
        float* __restrict__ out) {
    __shared__ float sW2[H2 * H2];
    __shared__ float sb2[H2];
    __shared__ float sW3[H2];
    __shared__ float sb3;
    for (int i = threadIdx.x; i < H2 * H2; i += blockDim.x) sW2[i] = W2[i];
    if (threadIdx.x < H2) { sb2[threadIdx.x] = b2[threadIdx.x]; sW3[threadIdx.x] = W3[threadIdx.x]; }
    if (threadIdx.x == 0) sb3 = b3[0];
    __syncthreads();

    cudaGridDependencySynchronize();   // wait for node_mlp's g_g

    int g = blockIdx.x * blockDim.x + threadIdx.x;
    if (g >= N_GRAPHS) return;

    float v[H2];
    const float2* gp = (const float2*)(g_g + (size_t)g * H2);
#pragma unroll
    for (int q = 0; q < 5; q++) {
        float2 t = gp[q];
        v[2*q] = t.x; v[2*q+1] = t.y;
    }

    float o = sb3;
#pragma unroll
    for (int j = 0; j < H2; j++) {
        float h = sb2[j];
#pragma unroll
        for (int k = 0; k < H2; k++) h = fmaf(v[k], sW2[k * H2 + j], h);
        o = fmaf(fmaxf(h, 0.f), sW3[j], o);
    }
    out[g] = o;
}

// ---------------------------------------------------------------------------
extern "C" void kernel_launch(void* const* d_in, const int* in_sizes, int n_in,
                              void* d_out, int out_size) {
    const int*   edge_index = (const int*)  d_in[0];
    const float* node_attr  = (const float*)d_in[1];
    const float* edge_attr  = (const float*)d_in[2];
    const int*   batch      = (const int*)  d_in[3];
    const float* W_msg      = (const float*)d_in[4];
    const float* b_msg      = (const float*)d_in[5];
    const float* W1         = (const float*)d_in[6];
    const float* b1         = (const float*)d_in[7];
    const float* W2         = (const float*)d_in[8];
    const float* b2         = (const float*)d_in[9];
    const float* W3         = (const float*)d_in[10];
    const float* b3         = (const float*)d_in[11];
    float* out = (float*)d_out;

    node_proj_kernel<<<(N_NODES + 127) / 128, 128>>>(node_attr, W_msg);

    cudaLaunchAttribute attr[1];
    attr[0].id = cudaLaunchAttributeProgrammaticStreamSerialization;
    attr[0].val.programmaticStreamSerializationAllowed = 1;

    {
        cudaLaunchConfig_t cfg = {};
        cfg.gridDim  = dim3((N_EDGES + 255) / 256);
        cfg.blockDim = dim3(256);
        cfg.attrs = attr; cfg.numAttrs = 1;
        cudaLaunchKernelEx(&cfg, edge_kernel, edge_index, edge_attr, W_msg, b_msg);
    }
    {
        cudaLaunchConfig_t cfg = {};
        cfg.gridDim  = dim3((N_NODES + 127) / 128);
        cfg.blockDim = dim3(128);
        cfg.attrs = attr; cfg.numAttrs = 1;
        cudaLaunchKernelEx(&cfg, node_mlp_kernel, batch, W1, b1);
    }
    {
        cudaLaunchConfig_t cfg = {};
        cfg.gridDim  = dim3((N_GRAPHS + 255) / 256);
        cfg.blockDim = dim3(256);
        cfg.attrs = attr; cfg.numAttrs = 1;
        cudaLaunchKernelEx(&cfg, graph_mlp_kernel, W2, b2, W3, b3, out);
    }
}

// round 17
// speedup vs baseline: 1.6952x; 1.0169x over previous
#include <cuda_runtime.h>
#include <cuda_fp16.h>

#define N_NODES   100000
#define N_EDGES   1600000
#define N_GRAPHS  5000
#define ND        16
#define ED        16
#define HID       20
#define H2        10
#define HP        (HID/2)
#define H2P       (H2/2)
#define PH_STRIDE 32        // half stride per pa/pb row: 64B
#define XH_STRIDE 32        // half stride per g_x row: 64B
#define GSTRIDE   12        // float stride per g_g row: 48B (16B-aligned v4 targets)

// Scratch
__device__ __align__(128) __half g_x [N_NODES * XH_STRIDE];  // fp16 accumulators
__device__ __align__(128) __half g_pa[N_NODES * PH_STRIDE];
__device__ __align__(128) __half g_pb[N_NODES * PH_STRIDE];
__device__ __align__(128) float g_g [N_GRAPHS * GSTRIDE];

// ---- packed f32x2 helpers -------------------------------------------------
__device__ __forceinline__ unsigned long long fma2(unsigned long long a,
                                                   unsigned long long b,
                                                   unsigned long long c) {
    unsigned long long d;
    asm("fma.rn.f32x2 %0, %1, %2, %3;" : "=l"(d) : "l"(a), "l"(b), "l"(c));
    return d;
}
__device__ __forceinline__ unsigned long long bcast2(float x) {
    unsigned long long d;
    asm("mov.b64 %0, {%1, %1};" : "=l"(d) : "f"(x));
    return d;
}
__device__ __forceinline__ float2 unpack2(unsigned long long v) {
    float2 r;
    asm("mov.b64 {%0, %1}, %2;" : "=f"(r.x), "=f"(r.y) : "l"(v));
    return r;
}
__device__ __forceinline__ float2 h2f2(unsigned int h) {
    return __half22float2(*(const __half2*)&h);
}

// 256-bit load (Blackwell) — requires 32B-aligned address
__device__ __forceinline__ void ldg256(const void* p, float r[8]) {
    asm("ld.global.nc.v8.f32 {%0,%1,%2,%3,%4,%5,%6,%7}, [%8];"
        : "=f"(r[0]), "=f"(r[1]), "=f"(r[2]), "=f"(r[3]),
          "=f"(r[4]), "=f"(r[5]), "=f"(r[6]), "=f"(r[7])
        : "l"(p));
}
__device__ __forceinline__ float2 ldg64(const void* p) {
    float2 r;
    asm("ld.global.nc.v2.f32 {%0,%1}, [%2];" : "=f"(r.x), "=f"(r.y) : "l"(p));
    return r;
}

// ---------------------------------------------------------------------------
// Kernel 1: per-node projections pa = A@Wa, pb = A@Wb  (fp16 out, + zeroing)
// ---------------------------------------------------------------------------
__global__ __launch_bounds__(128) void node_proj_kernel(
        const float* __restrict__ node_attr,
        const float* __restrict__ W_msg) {
    __shared__ __align__(8) float sWa[ND * HID];
    __shared__ __align__(8) float sWb[ND * HID];
    for (int i = threadIdx.x; i < ND * HID; i += blockDim.x) {
        sWa[i] = W_msg[i];
        sWb[i] = W_msg[ND * HID + i];
    }
    __syncthreads();
    const unsigned long long* wa2 = (const unsigned long long*)sWa;
    const unsigned long long* wb2 = (const unsigned long long*)sWb;

    int n = blockIdx.x * blockDim.x + threadIdx.x;

    if (n < (N_GRAPHS * GSTRIDE) / 4)
        ((float4*)g_g)[n] = make_float4(0.f, 0.f, 0.f, 0.f);

    if (n >= N_NODES) return;

    // zero this node's fp16 g_x row
    {
        char* xr = (char*)g_x + (size_t)n * 64;
        const uint4 z4 = make_uint4(0u, 0u, 0u, 0u);
        *(uint4*)(xr)      = z4;
        *(uint4*)(xr + 16) = z4;
        *(uint2*)(xr + 32) = make_uint2(0u, 0u);
    }

    float a[ND];
    const float4* ap = (const float4*)(node_attr + (size_t)n * ND);
#pragma unroll
    for (int q = 0; q < 4; q++) {
        float4 v = ap[q];
        a[4*q+0] = v.x; a[4*q+1] = v.y; a[4*q+2] = v.z; a[4*q+3] = v.w;
    }

    unsigned long long acc[HP];
    unsigned int u[HP];

    // pa
#pragma unroll
    for (int p = 0; p < HP; p++) acc[p] = 0ull;
#pragma unroll
    for (int k = 0; k < ND; k++) {
        unsigned long long ak = bcast2(a[k]);
#pragma unroll
        for (int p = 0; p < HP; p++) acc[p] = fma2(ak, wa2[k * HP + p], acc[p]);
    }
#pragma unroll
    for (int p = 0; p < HP; p++) {
        float2 t = unpack2(acc[p]);
        __half2 h = __float22half2_rn(t);
        u[p] = *(unsigned int*)&h;
    }
    {
        char* row = (char*)(g_pa + (size_t)n * PH_STRIDE);
        *(uint4*)(row +  0) = make_uint4(u[0], u[1], u[2], u[3]);
        *(uint4*)(row + 16) = make_uint4(u[4], u[5], u[6], u[7]);
        *(uint2*)(row + 32) = make_uint2(u[8], u[9]);
    }

    // pb
#pragma unroll
    for (int p = 0; p < HP; p++) acc[p] = 0ull;
#pragma unroll
    for (int k = 0; k < ND; k++) {
        unsigned long long ak = bcast2(a[k]);
#pragma unroll
        for (int p = 0; p < HP; p++) acc[p] = fma2(ak, wb2[k * HP + p], acc[p]);
    }
#pragma unroll
    for (int p = 0; p < HP; p++) {
        float2 t = unpack2(acc[p]);
        __half2 h = __float22half2_rn(t);
        u[p] = *(unsigned int*)&h;
    }
    {
        char* row = (char*)(g_pb + (size_t)n * PH_STRIDE);
        *(uint4*)(row +  0) = make_uint4(u[0], u[1], u[2], u[3]);
        *(uint4*)(row + 16) = make_uint4(u[4], u[5], u[6], u[7]);
        *(uint2*)(row + 32) = make_uint2(u[8], u[9]);
    }
}

// ---------------------------------------------------------------------------
// Kernel 2: edge message + scatter-sum (PDL consumer)
// ---------------------------------------------------------------------------
__global__ __launch_bounds__(256) void edge_kernel(
        const int*   __restrict__ edge_index,
        const float* __restrict__ edge_attr,
        const float* __restrict__ W_msg,
        const float* __restrict__ b_msg) {
    __shared__ __align__(8) float sWe[ED * HID];
    __shared__ __align__(8) float sb[HID];
    for (int i = threadIdx.x; i < ED * HID; i += blockDim.x)
        sWe[i] = W_msg[2 * ND * HID + i];
    for (int i = threadIdx.x; i < HID; i += blockDim.x)
        sb[i] = b_msg[i];
    __syncthreads();
    const unsigned long long* we2 = (const unsigned long long*)sWe;
    const unsigned long long* sb2 = (const unsigned long long*)sb;

    int e = blockIdx.x * blockDim.x + threadIdx.x;
    if (e >= N_EDGES) {
        cudaGridDependencySynchronize();
        return;
    }

    int src = __ldg(edge_index + e);
    int dst = __ldg(edge_index + N_EDGES + e);
    float ea[ED];
    ldg256(edge_attr + (size_t)e * ED, ea);
    ldg256(edge_attr + (size_t)e * ED + 8, ea + 8);

    cudaGridDependencySynchronize();

    const char* par = (const char*)(g_pa + (size_t)src * PH_STRIDE);
    const char* pbr = (const char*)(g_pb + (size_t)dst * PH_STRIDE);
    float A8[8], B8[8];
    ldg256(par, A8);
    ldg256(pbr, B8);
    float2 A2 = ldg64(par + 32);
    float2 B2 = ldg64(pbr + 32);

    unsigned long long acc[HP];
#pragma unroll
    for (int p = 0; p < HP; p++) acc[p] = sb2[p];
#pragma unroll
    for (int k = 0; k < ED; k++) {
        unsigned long long b = bcast2(ea[k]);
#pragma unroll
        for (int p = 0; p < HP; p++)
            acc[p] = fma2(b, we2[k * HP + p], acc[p]);
    }

    unsigned int au[HP] = {
        __float_as_uint(A8[0]), __float_as_uint(A8[1]), __float_as_uint(A8[2]),
        __float_as_uint(A8[3]), __float_as_uint(A8[4]), __float_as_uint(A8[5]),
        __float_as_uint(A8[6]), __float_as_uint(A8[7]),
        __float_as_uint(A2.x),  __float_as_uint(A2.y)};
    unsigned int bu[HP] = {
        __float_as_uint(B8[0]), __float_as_uint(B8[1]), __float_as_uint(B8[2]),
        __float_as_uint(B8[3]), __float_as_uint(B8[4]), __float_as_uint(B8[5]),
        __float_as_uint(B8[6]), __float_as_uint(B8[7]),
        __float_as_uint(B2.x),  __float_as_uint(B2.y)};

    unsigned int mh[HP];
#pragma unroll
    for (int p = 0; p < HP; p++) {
        float2 c = unpack2(acc[p]);
        float2 fa = h2f2(au[p]);
        float2 fb = h2f2(bu[p]);
        float2 mm;
        mm.x = fmaxf(c.x + fa.x + fb.x, 0.f);
        mm.y = fmaxf(c.y + fa.y + fb.y, 0.f);
        __half2 h = __float22half2_rn(mm);
        mh[p] = *(unsigned int*)&h;
    }

    char* xr = (char*)g_x + (size_t)dst * 64;
    asm volatile("red.global.add.noftz.v4.f16x2 [%0], {%1,%2,%3,%4};"
                 :: "l"(xr), "r"(mh[0]), "r"(mh[1]), "r"(mh[2]), "r"(mh[3]) : "memory");
    asm volatile("red.global.add.noftz.v4.f16x2 [%0], {%1,%2,%3,%4};"
                 :: "l"(xr + 16), "r"(mh[4]), "r"(mh[5]), "r"(mh[6]), "r"(mh[7]) : "memory");
    asm volatile("red.global.add.noftz.v2.f16x2 [%0], {%1,%2};"
                 :: "l"(xr + 32), "r"(mh[8]), "r"(mh[9]) : "memory");
}

// ---------------------------------------------------------------------------
// Kernel 3: node MLP + graph pooling (3-op v4/v4/v2 pooling scatter)
// ---------------------------------------------------------------------------
__global__ __launch_bounds__(128) void node_mlp_kernel(
        const int*   __restrict__ batch,
        const float* __restrict__ W1,
        const float* __restrict__ b1) {
    __shared__ __align__(8) float sW[HID * H2];
    __shared__ __align__(8) float sb[H2];
    for (int i = threadIdx.x; i < HID * H2; i += blockDim.x) sW[i] = W1[i];
    for (int i = threadIdx.x; i < H2; i += blockDim.x) sb[i] = b1[i];
    __syncthreads();
    const unsigned long long* w2 = (const unsigned long long*)sW;
    const unsigned long long* sb2 = (const unsigned long long*)sb;

    int n = blockIdx.x * blockDim.x + threadIdx.x;
    if (n >= N_NODES) {
        cudaGridDependencySynchronize();
        return;
    }

    int b = __ldg(batch + n);     // input, safe before sync

    cudaGridDependencySynchronize();   // wait for edge_kernel's g_x

    const char* xrow = (const char*)g_x + (size_t)n * 64;
    float X8[8];
    ldg256(xrow, X8);
    float2 X2 = ldg64(xrow + 32);
    unsigned int xu[HP] = {
        __float_as_uint(X8[0]), __float_as_uint(X8[1]), __float_as_uint(X8[2]),
        __float_as_uint(X8[3]), __float_as_uint(X8[4]), __float_as_uint(X8[5]),
        __float_as_uint(X8[6]), __float_as_uint(X8[7]),
        __float_as_uint(X2.x),  __float_as_uint(X2.y)};

    float x[HID];
#pragma unroll
    for (int p = 0; p < HP; p++) {
        float2 t = h2f2(xu[p]);
        x[2*p] = t.x; x[2*p+1] = t.y;
    }

    unsigned long long acc[H2P];
#pragma unroll
    for (int p = 0; p < H2P; p++) acc[p] = sb2[p];
#pragma unroll
    for (int k = 0; k < HID; k++) {
        unsigned long long xk = bcast2(x[k]);
#pragma unroll
        for (int p = 0; p < H2P; p++) acc[p] = fma2(xk, w2[k * H2P + p], acc[p]);
    }

    float y[H2];
#pragma unroll
    for (int p = 0; p < H2P; p++) {
        float2 t = unpack2(acc[p]);
        y[2*p]   = fmaxf(t.x, 0.f);
        y[2*p+1] = fmaxf(t.y, 0.f);
    }

    // 3-op pooling scatter into 48B-stride g_g rows
    float* gr = g_g + (size_t)b * GSTRIDE;
    asm volatile("red.global.add.v4.f32 [%0], {%1,%2,%3,%4};"
                 :: "l"(gr), "f"(y[0]), "f"(y[1]), "f"(y[2]), "f"(y[3]) : "memory");
    asm volatile("red.global.add.v4.f32 [%0], {%1,%2,%3,%4};"
                 :: "l"(gr + 4), "f"(y[4]), "f"(y[5]), "f"(y[6]), "f"(y[7]) : "memory");
    asm volatile("red.global.add.v2.f32 [%0], {%1,%2};"
                 :: "l"(gr + 8), "f"(y[8]), "f"(y[9]) : "memory");
}

// ---------------------------------------------------------------------------
// Kernel 4: graph MLP (PDL consumer; 48B-stride g_g reads)
// ---------------------------------------------------------------------------
__global__ __launch_bounds__(256) void graph_mlp_kernel(
        const float* __restrict__ W2,
        const float* __restrict__ b2,
        const float* __restrict__ W3,
        const float* __restrict__ b3,
        float* __restrict__ out) {
    __shared__ float sW2[H2 * H2];
    __shared__ float sb2[H2];
    __shared__ float sW3[H2];
    __shared__ float sb3;
    for (int i = threadIdx.x; i < H2 * H2; i += blockDim.x) sW2[i] = W2[i];
    if (threadIdx.x < H2) { sb2[threadIdx.x] = b2[threadIdx.x]; sW3[threadIdx.x] = W3[threadIdx.x]; }
    if (threadIdx.x == 0) sb3 = b3[0];
    __syncthreads();

    cudaGridDependencySynchronize();   // wait for node_mlp's g_g

    int g = blockIdx.x * blockDim.x + threadIdx.x;
    if (g >= N_GRAPHS) return;

    float v[H2];
    const float2* gp = (const float2*)(g_g + (size_t)g * GSTRIDE);
#pragma unroll
    for (int q = 0; q < 5; q++) {
        float2 t = gp[q];
        v[2*q] = t.x; v[2*q+1] = t.y;
    }

    float o = sb3;
#pragma unroll
    for (int j = 0; j < H2; j++) {
        float h = sb2[j];
#pragma unroll
        for (int k = 0; k < H2; k++) h = fmaf(v[k], sW2[k * H2 + j], h);
        o = fmaf(fmaxf(h, 0.f), sW3[j], o);
    }
    out[g] = o;
}

// ---------------------------------------------------------------------------
extern "C" void kernel_launch(void* const* d_in, const int* in_sizes, int n_in,
                              void* d_out, int out_size) {
    const int*   edge_index = (const int*)  d_in[0];
    const float* node_attr  = (const float*)d_in[1];
    const float* edge_attr  = (const float*)d_in[2];
    const int*   batch      = (const int*)  d_in[3];
    const float* W_msg      = (const float*)d_in[4];
    const float* b_msg      = (const float*)d_in[5];
    const float* W1         = (const float*)d_in[6];
    const float* b1         = (const float*)d_in[7];
    const float* W2         = (const float*)d_in[8];
    const float* b2         = (const float*)d_in[9];
    const float* W3         = (const float*)d_in[10];
    const float* b3         = (const float*)d_in[11];
    float* out = (float*)d_out;

    node_proj_kernel<<<(N_NODES + 127) / 128, 128>>>(node_attr, W_msg);

    cudaLaunchAttribute attr[1];
    attr[0].id = cudaLaunchAttributeProgrammaticStreamSerialization;
    attr[0].val.programmaticStreamSerializationAllowed = 1;

    {
        cudaLaunchConfig_t cfg = {};
        cfg.gridDim  = dim3((N_EDGES + 255) / 256);
        cfg.blockDim = dim3(256);
        cfg.attrs = attr; cfg.numAttrs = 1;
        cudaLaunchKernelEx(&cfg, edge_kernel, edge_index, edge_attr, W_msg, b_msg);
    }
    {
        cudaLaunchConfig_t cfg = {};
        cfg.gridDim  = dim3((N_NODES + 127) / 128);
        cfg.blockDim = dim3(128);
        cfg.attrs = attr; cfg.numAttrs = 1;
        cudaLaunchKernelEx(&cfg, node_mlp_kernel, batch, W1, b1);
    }
    {
        cudaLaunchConfig_t cfg = {};
        cfg.gridDim  = dim3((N_GRAPHS + 255) / 256);
        cfg.blockDim = dim3(256);
        cfg.attrs = attr; cfg.numAttrs = 1;
        cudaLaunchKernelEx(&cfg, graph_mlp_kernel, W2, b2, W3, b3, out);
    }
}